// round 2
// baseline (speedup 1.0000x reference)
#include <cuda_runtime.h>
#include <cstdint>

// ---------------------------------------------------------------------------
// ChaoticLSTM: bs=64, seq=512, in=128, H=256, 4H=1024, T=512
//   Phase 1: xproj[32768][1024] = X[32768][128] @ Wi[128][1024] + B
//   Phase 2: persistent recurrence kernel, 128 CTAs, grid barrier per step.
// Output layout: output[64][512][256], ht[64][256], ct[64][256]
// ---------------------------------------------------------------------------

#define NBLK 128
#define NT   256
#define HP   260     // hsh row pitch (floats), padded for bank spread
#define WP   260     // Wsh row pitch

typedef unsigned long long ull;

__device__ float    g_xproj[32768u * 1024u];   // 128 MB scratch
__device__ float    g_hbuf[2][64 * 256];       // double-buffered h state
__device__ unsigned g_bar_cnt;                 // zero-init; self-resetting
__device__ unsigned g_bar_phase;               // monotonic across replays

__device__ __forceinline__ void fma2(ull& d, ull a, ull b) {
    asm("fma.rn.f32x2 %0, %1, %2, %0;" : "+l"(d) : "l"(a), "l"(b));
}
__device__ __forceinline__ ull splat2(float x) {
    ull r; asm("mov.b64 %0, {%1, %1};" : "=l"(r) : "f"(x)); return r;
}
__device__ __forceinline__ float2 unpack2(ull v) {
    float2 r; asm("mov.b64 {%0, %1}, %2;" : "=f"(r.x), "=f"(r.y) : "l"(v)); return r;
}
__device__ __forceinline__ float sigmoidf_(float x) {
    return 1.0f / (1.0f + __expf(-x));
}

// ---------------------------------------------------------------------------
// Phase 1: xproj GEMM. Block tile 64(M) x 64(N), full K=128 in 4 chunks of 32.
// Thread tile 4x4 using fma.rn.f32x2 (pairs over N).
// ---------------------------------------------------------------------------
__global__ __launch_bounds__(256) void xproj_kernel(const float* __restrict__ X,
                                                    const float* __restrict__ Wi,
                                                    const float* __restrict__ Bias) {
    __shared__ __align__(16) float As_t[32 * 68];  // [k][m], padded
    __shared__ __align__(16) float Bs[32 * 64];    // [k][n]

    const int tid = threadIdx.x;
    const int m0 = blockIdx.y * 64;
    const int n0 = blockIdx.x * 64;
    const int tm = tid >> 4, tn = tid & 15;

    ull acc[4][2];
#pragma unroll
    for (int i = 0; i < 4; ++i) { acc[i][0] = 0ull; acc[i][1] = 0ull; }

    const float4* X4  = (const float4*)X;
    const float4* Wi4 = (const float4*)Wi;

    for (int kt = 0; kt < 128; kt += 32) {
#pragma unroll
        for (int i = 0; i < 2; ++i) {       // A: 64 rows x 32 k, transpose into smem
            int f = tid + i * 256;          // 512 float4s
            int row = f >> 3, kk4 = f & 7;
            float4 v = X4[(size_t)(m0 + row) * 32 + (kt >> 2) + kk4];
            As_t[(kk4 * 4 + 0) * 68 + row] = v.x;
            As_t[(kk4 * 4 + 1) * 68 + row] = v.y;
            As_t[(kk4 * 4 + 2) * 68 + row] = v.z;
            As_t[(kk4 * 4 + 3) * 68 + row] = v.w;
        }
#pragma unroll
        for (int i = 0; i < 2; ++i) {       // B: 32 k-rows x 64 n
            int f = tid + i * 256;
            int row = f >> 4, c4 = f & 15;
            *(float4*)(Bs + row * 64 + c4 * 4) =
                Wi4[(size_t)(kt + row) * 256 + (n0 >> 2) + c4];
        }
        __syncthreads();
#pragma unroll
        for (int kk = 0; kk < 32; ++kk) {
            float4 a4 = *(const float4*)(As_t + kk * 68 + tm * 4);
            ulonglong2 b2 = *(const ulonglong2*)(Bs + kk * 64 + tn * 4);
            ull s;
            s = splat2(a4.x); fma2(acc[0][0], s, b2.x); fma2(acc[0][1], s, b2.y);
            s = splat2(a4.y); fma2(acc[1][0], s, b2.x); fma2(acc[1][1], s, b2.y);
            s = splat2(a4.z); fma2(acc[2][0], s, b2.x); fma2(acc[2][1], s, b2.y);
            s = splat2(a4.w); fma2(acc[3][0], s, b2.x); fma2(acc[3][1], s, b2.y);
        }
        __syncthreads();
    }

    float4 bias = *(const float4*)(Bias + n0 + tn * 4);
#pragma unroll
    for (int i = 0; i < 4; ++i) {
        float2 p0 = unpack2(acc[i][0]);
        float2 p1 = unpack2(acc[i][1]);
        float4 o = make_float4(p0.x + bias.x, p0.y + bias.y,
                               p1.x + bias.z, p1.y + bias.w);
        *(float4*)(g_xproj + (size_t)(m0 + tm * 4 + i) * 1024 + n0 + tn * 4) = o;
    }
}

// ---------------------------------------------------------------------------
// Phase 2: persistent recurrence. 128 CTAs x 256 threads.
// CTA bid owns h-dims {2*bid, 2*bid+1}; per h-dim the 4 gate columns
// {j, 256+j, 512+j, 768+j}. Wh slice (8 cols x 256) lives in smem for all
// 512 steps. h is exchanged through a double-buffered global array with a
// hand-rolled grid barrier per step.
// Thread (b = tid>>2, g = tid&3) computes gates[b][gate g][both h-dims]
// as f32x2 dot products (even/odd-k partials packed, no splat MOVs needed).
// Threads 0..127 own the cell state: (b = tid>>1, jj = tid&1).
// ---------------------------------------------------------------------------
__global__ __launch_bounds__(256, 1) void lstm_rec(const float* __restrict__ Wh,
                                                   float* __restrict__ out,
                                                   int out_size) {
    extern __shared__ __align__(16) float sm[];
    float* hsh = sm;                 // 64 * HP
    float* Wsh = sm + 64 * HP;       // 8 * WP
    float* gsh = Wsh + 8 * WP;       // 64 * 8

    const int tid = threadIdx.x;
    const int j0 = blockIdx.x * 2;

    // Load this CTA's Wh slice, transposed: Wsh[c][k], c = g*2 + jj.
    for (int idx = tid; idx < 8 * 256; idx += NT) {
        int r = idx >> 8, k = idx & 255;
        Wsh[r * WP + k] = Wh[k * 1024 + (r >> 1) * 256 + j0 + (r & 1)];
    }

    unsigned gen = 0;
    if (tid == 0) {
        asm volatile("ld.acquire.gpu.global.u32 %0, [%1];"
                     : "=r"(gen) : "l"(&g_bar_phase) : "memory");
    }

    const int b = tid >> 2, g = tid & 3;
    const ulonglong2* wr0 = (const ulonglong2*)(Wsh + (g * 2 + 0) * WP);
    const ulonglong2* wr1 = (const ulonglong2*)(Wsh + (g * 2 + 1) * WP);
    const ulonglong2* hr  = (const ulonglong2*)(hsh + b * HP);

    const int cb = tid >> 1, cj = tid & 1;   // cell mapping for tid < 128
    float creg = 0.0f, hlast = 0.0f;

    __syncthreads();   // Wsh ready

    for (int t = 0; t < 512; ++t) {
        if (t > 0) {
            // ---- grid barrier (sense-counting, replay-safe) ----
            __syncthreads();
            if (tid == 0) {
                __threadfence();
                unsigned a = atomicAdd(&g_bar_cnt, 1u);
                unsigned target = gen + 1u;
                if (a == NBLK - 1) {
                    g_bar_cnt = 0;
                    __threadfence();
                    asm volatile("st.release.gpu.global.u32 [%0], %1;"
                                 :: "l"(&g_bar_phase), "r"(target) : "memory");
                } else {
                    unsigned v;
                    do {
                        asm volatile("ld.acquire.gpu.global.u32 %0, [%1];"
                                     : "=r"(v) : "l"(&g_bar_phase) : "memory");
                    } while (v != target);
                }
                gen = target;
            }
            __syncthreads();

            // ---- stage h(t-1) into smem (L2-coherent loads) ----
            const float4* src = (const float4*)(g_hbuf[(t - 1) & 1]);
#pragma unroll
            for (int i = 0; i < 16; ++i) {
                int f = i * 256 + tid;
                float4 v = __ldcg(src + f);
                *(float4*)(hsh + (f >> 6) * HP + (f & 63) * 4) = v;
            }
            __syncthreads();
        }

        const int c0 = g * 256 + j0;
        float2 xpv = *(const float2*)(g_xproj + (size_t)(b * 512 + t) * 1024 + c0);
        float g0 = xpv.x, g1 = xpv.y;

        if (t > 0) {
            ull a0a = 0, a0b = 0, a1a = 0, a1b = 0;
#pragma unroll 8
            for (int k4 = 0; k4 < 64; ++k4) {
                ulonglong2 hv = hr[k4];
                ulonglong2 w0 = wr0[k4];
                ulonglong2 w1 = wr1[k4];
                fma2(a0a, w0.x, hv.x); fma2(a0b, w0.y, hv.y);
                fma2(a1a, w1.x, hv.x); fma2(a1b, w1.y, hv.y);
            }
            float2 p;
            p = unpack2(a0a); g0 += p.x + p.y;
            p = unpack2(a0b); g0 += p.x + p.y;
            p = unpack2(a1a); g1 += p.x + p.y;
            p = unpack2(a1b); g1 += p.x + p.y;
        }

        float act0, act1;
        if (g == 2) { act0 = tanhf(g0);     act1 = tanhf(g1); }
        else        { act0 = sigmoidf_(g0); act1 = sigmoidf_(g1); }
        gsh[b * 8 + g * 2 + 0] = act0;
        gsh[b * 8 + g * 2 + 1] = act1;
        __syncthreads();

        if (tid < 128) {
            float i_ = gsh[cb * 8 + 0 + cj];
            float f_ = gsh[cb * 8 + 2 + cj];
            float gg = gsh[cb * 8 + 4 + cj];
            float o_ = gsh[cb * 8 + 6 + cj];
            creg = f_ * creg + i_ * gg;
            float hn = o_ * tanhf(creg);
            hlast = hn;
            __stcg(&g_hbuf[t & 1][cb * 256 + j0 + cj], hn);
            out[(size_t)(cb * 512 + t) * 256 + j0 + cj] = hn;
        }
        // gsh/hsh WAR across iterations is protected by the barrier's syncthreads.
    }

    if (tid < 128 && out_size >= 8421376) {
        out[8388608u + cb * 256 + j0 + cj]          = hlast;   // ht
        out[8388608u + 16384u + cb * 256 + j0 + cj] = creg;    // ct
    }
}

// ---------------------------------------------------------------------------
extern "C" void kernel_launch(void* const* d_in, const int* in_sizes, int n_in,
                              void* d_out, int out_size) {
    // Robust input identification by element count.
    const float* x  = nullptr;   // 64*512*128 = 4194304
    const float* Wi = nullptr;   // 128*1024   = 131072
    const float* Wh = nullptr;   // 256*1024   = 262144
    const float* Bb = nullptr;   // 1024
    for (int i = 0; i < n_in; ++i) {
        switch (in_sizes[i]) {
            case 4194304: x  = (const float*)d_in[i]; break;
            case 131072:  Wi = (const float*)d_in[i]; break;
            case 262144:  Wh = (const float*)d_in[i]; break;
            case 1024:    Bb = (const float*)d_in[i]; break;
            default: break;
        }
    }
    float* out = (float*)d_out;

    const int rec_smem = (64 * HP + 8 * WP + 64 * 8) * (int)sizeof(float); // 76928 B
    cudaFuncSetAttribute(lstm_rec, cudaFuncAttributeMaxDynamicSharedMemorySize,
                         rec_smem);

    xproj_kernel<<<dim3(16, 512), 256>>>(x, Wi, Bb);
    lstm_rec<<<NBLK, NT, rec_smem>>>(Wh, out, out_size);
}

// round 3
// speedup vs baseline: 1.2017x; 1.2017x over previous
#include <cuda_runtime.h>
#include <cstdint>

// ---------------------------------------------------------------------------
// ChaoticLSTM: bs=64, seq=512, in=128, H=256, 4H=1024, T=512
//   Phase 1: xproj[32768][1024] = X[32768][128] @ Wi[128][1024] + B  (unchanged)
//   Phase 2: register-stationary-Wh recurrence.
//     grid = 128 CTAs x 512 thr = 16 clusters of 8 CTAs.
//     cluster = one batch-group (4 batches); CTA rank r owns h-dims [32r,32r+32)
//     and their 4 gate columns. Wh slice lives in REGISTERS (32 f32x2/thread).
//     h(t) exchanged via DSMEM push + barrier.cluster (no global barrier,
//     no mutable global state -> replay-safe by construction).
// ---------------------------------------------------------------------------

typedef unsigned long long ull;

__device__ float g_xproj[32768u * 1024u];   // 128 MB scratch

__device__ __forceinline__ void fma2(ull& d, ull a, ull b) {
    asm("fma.rn.f32x2 %0, %1, %2, %0;" : "+l"(d) : "l"(a), "l"(b));
}
__device__ __forceinline__ ull splat2(float x) {
    ull r; asm("mov.b64 %0, {%1, %1};" : "=l"(r) : "f"(x)); return r;
}
__device__ __forceinline__ ull pack2(float a, float b) {
    ull r; asm("mov.b64 %0, {%1, %2};" : "=l"(r) : "f"(a), "f"(b)); return r;
}
__device__ __forceinline__ float2 unpack2(ull v) {
    float2 r; asm("mov.b64 {%0, %1}, %2;" : "=f"(r.x), "=f"(r.y) : "l"(v)); return r;
}
__device__ __forceinline__ float sigmoidf_(float x) {
    return 1.0f / (1.0f + __expf(-x));
}
__device__ __forceinline__ uint32_t smem_u32(const void* p) {
    uint32_t a;
    asm("{ .reg .u64 t; cvta.to.shared.u64 t, %1; cvt.u32.u64 %0, t; }"
        : "=r"(a) : "l"(p));
    return a;
}

// ---------------------------------------------------------------------------
// Phase 1: xproj GEMM (unchanged from R2 — correct, ~200us).
// ---------------------------------------------------------------------------
__global__ __launch_bounds__(256) void xproj_kernel(const float* __restrict__ X,
                                                    const float* __restrict__ Wi,
                                                    const float* __restrict__ Bias) {
    __shared__ __align__(16) float As_t[32 * 68];
    __shared__ __align__(16) float Bs[32 * 64];

    const int tid = threadIdx.x;
    const int m0 = blockIdx.y * 64;
    const int n0 = blockIdx.x * 64;
    const int tm = tid >> 4, tn = tid & 15;

    ull acc[4][2];
#pragma unroll
    for (int i = 0; i < 4; ++i) { acc[i][0] = 0ull; acc[i][1] = 0ull; }

    const float4* X4  = (const float4*)X;
    const float4* Wi4 = (const float4*)Wi;

    for (int kt = 0; kt < 128; kt += 32) {
#pragma unroll
        for (int i = 0; i < 2; ++i) {
            int f = tid + i * 256;
            int row = f >> 3, kk4 = f & 7;
            float4 v = X4[(size_t)(m0 + row) * 32 + (kt >> 2) + kk4];
            As_t[(kk4 * 4 + 0) * 68 + row] = v.x;
            As_t[(kk4 * 4 + 1) * 68 + row] = v.y;
            As_t[(kk4 * 4 + 2) * 68 + row] = v.z;
            As_t[(kk4 * 4 + 3) * 68 + row] = v.w;
        }
#pragma unroll
        for (int i = 0; i < 2; ++i) {
            int f = tid + i * 256;
            int row = f >> 4, c4 = f & 15;
            *(float4*)(Bs + row * 64 + c4 * 4) =
                Wi4[(size_t)(kt + row) * 256 + (n0 >> 2) + c4];
        }
        __syncthreads();
#pragma unroll
        for (int kk = 0; kk < 32; ++kk) {
            float4 a4 = *(const float4*)(As_t + kk * 68 + tm * 4);
            ulonglong2 b2 = *(const ulonglong2*)(Bs + kk * 64 + tn * 4);
            ull s;
            s = splat2(a4.x); fma2(acc[0][0], s, b2.x); fma2(acc[0][1], s, b2.y);
            s = splat2(a4.y); fma2(acc[1][0], s, b2.x); fma2(acc[1][1], s, b2.y);
            s = splat2(a4.z); fma2(acc[2][0], s, b2.x); fma2(acc[2][1], s, b2.y);
            s = splat2(a4.w); fma2(acc[3][0], s, b2.x); fma2(acc[3][1], s, b2.y);
        }
        __syncthreads();
    }

    float4 bias = *(const float4*)(Bias + n0 + tn * 4);
#pragma unroll
    for (int i = 0; i < 4; ++i) {
        float2 p0 = unpack2(acc[i][0]);
        float2 p1 = unpack2(acc[i][1]);
        float4 o = make_float4(p0.x + bias.x, p0.y + bias.y,
                               p1.x + bias.z, p1.y + bias.w);
        *(float4*)(g_xproj + (size_t)(m0 + tm * 4 + i) * 1024 + n0 + tn * 4) = o;
    }
}

// ---------------------------------------------------------------------------
// Phase 2: register-stationary recurrence.
//
// Thread layout per CTA (512 thr, 16 warps):
//   lane = s*8 + cl  (s = k-segment 0..3 of 64 k each; cl = col-low)
//   col  = warp*8 + cl  (0..127) = (gate ga = col>>5, jj = col&31)
//   global gate column = ga*256 + r*32 + jj   (r = cluster rank)
// Thread holds Wh[kseg][col] as 32 f32x2 registers for all 512 steps.
// h segments in smem have a 68-float skew so the 4 s-groups of a warp hit
// disjoint banks (conflict-free LDS.128 + 8-lane broadcast).
// Dot reduction: shfl.xor 8,16. Cell state in regs of threads 0..127.
// h(t) pushed to all 8 cluster CTAs' smem; one barrier.cluster per step.
// ---------------------------------------------------------------------------
__global__ __launch_bounds__(512, 1) __cluster_dims__(8, 1, 1)
void lstm_rec(const float* __restrict__ Wh, float* __restrict__ out) {
    __shared__ __align__(16) float hsm[2 * 4 * 272];   // [buf][batch][4 seg x 68]
    __shared__ float gsm[4 * 128];                     // [batch][ga*32+jj]

    const int tid  = threadIdx.x;
    const int lane = tid & 31;
    const int warp = tid >> 5;
    const int cl   = lane & 7;
    const int s    = lane >> 3;
    const int c    = warp * 8 + cl;          // 0..127
    const int ga   = c >> 5;
    const int jj   = c & 31;

    uint32_t rank;
    asm("mov.u32 %0, %%cluster_ctarank;" : "=r"(rank));
    const int r    = (int)rank;
    const int b0   = (blockIdx.x >> 3) * 4;  // first batch of this cluster
    const int colg = ga * 256 + r * 32 + jj;
    const int kbase = s * 64;

    // --- Wh slice -> registers (one-time; Wh fits L2, heavily reused) ---
    ull wreg[32];
#pragma unroll
    for (int i = 0; i < 32; ++i) {
        float wa = __ldg(&Wh[(size_t)(kbase + 2 * i) * 1024 + colg]);
        float wb = __ldg(&Wh[(size_t)(kbase + 2 * i + 1) * 1024 + colg]);
        wreg[i] = pack2(wa, wb);
    }

    // zero both h buffers (h(-1) = 0)
    for (int i = tid; i < 2 * 4 * 272; i += 512) hsm[i] = 0.0f;
    __syncthreads();

    const uint32_t hsm_base = smem_u32(hsm);

    // cell-thread constants (valid for tid < 128)
    const int cb   = tid >> 5;               // batch 0..3
    const int cj   = tid & 31;               // h-dim within this CTA's 32
    const int koff = r * 32 + cj;            // global h index
    const int cell_off = (koff >> 6) * 68 + (koff & 63);
    float cre = 0.0f, hlast = 0.0f;

    const float* xpp0 = g_xproj + (size_t)b0 * 512 * 1024 + colg;

    for (int t = 0; t < 512; ++t) {
        const int pb = (t + 1) & 1;          // previous-h buffer
        const float* hb = hsm + pb * (4 * 272);

        // prefetch xproj for this step (only reducer lanes need it)
        float xp0, xp1, xp2, xp3;
        if (lane < 8) {
            const float* xpp = xpp0 + (size_t)t * 1024;
            xp0 = __ldg(xpp);
            xp1 = __ldg(xpp + 1 * 512 * 1024);
            xp2 = __ldg(xpp + 2 * 512 * 1024);
            xp3 = __ldg(xpp + 3 * 512 * 1024);
        }

        const ulonglong2* h0 = (const ulonglong2*)(hb + 0 * 272 + s * 68);
        const ulonglong2* h1 = (const ulonglong2*)(hb + 1 * 272 + s * 68);
        const ulonglong2* h2 = (const ulonglong2*)(hb + 2 * 272 + s * 68);
        const ulonglong2* h3 = (const ulonglong2*)(hb + 3 * 272 + s * 68);

        ull a0 = 0, a1 = 0, a2 = 0, a3 = 0;
#pragma unroll
        for (int i = 0; i < 16; ++i) {
            ulonglong2 v0 = h0[i];
            ulonglong2 v1 = h1[i];
            ulonglong2 v2 = h2[i];
            ulonglong2 v3 = h3[i];
            fma2(a0, wreg[2 * i], v0.x); fma2(a0, wreg[2 * i + 1], v0.y);
            fma2(a1, wreg[2 * i], v1.x); fma2(a1, wreg[2 * i + 1], v1.y);
            fma2(a2, wreg[2 * i], v2.x); fma2(a2, wreg[2 * i + 1], v2.y);
            fma2(a3, wreg[2 * i], v3.x); fma2(a3, wreg[2 * i + 1], v3.y);
        }

        float2 p;
        float d0, d1, d2, d3;
        p = unpack2(a0); d0 = p.x + p.y;
        p = unpack2(a1); d1 = p.x + p.y;
        p = unpack2(a2); d2 = p.x + p.y;
        p = unpack2(a3); d3 = p.x + p.y;

        // reduce across the 4 k-segments (lanes xor 8, 16)
        d0 += __shfl_xor_sync(0xffffffffu, d0, 8);
        d1 += __shfl_xor_sync(0xffffffffu, d1, 8);
        d2 += __shfl_xor_sync(0xffffffffu, d2, 8);
        d3 += __shfl_xor_sync(0xffffffffu, d3, 8);
        d0 += __shfl_xor_sync(0xffffffffu, d0, 16);
        d1 += __shfl_xor_sync(0xffffffffu, d1, 16);
        d2 += __shfl_xor_sync(0xffffffffu, d2, 16);
        d3 += __shfl_xor_sync(0xffffffffu, d3, 16);

        if (lane < 8) {
            float g0 = xp0 + d0, g1 = xp1 + d1, g2 = xp2 + d2, g3 = xp3 + d3;
            float e0, e1, e2, e3;
            if (ga == 2) {
                e0 = tanhf(g0); e1 = tanhf(g1); e2 = tanhf(g2); e3 = tanhf(g3);
            } else {
                e0 = sigmoidf_(g0); e1 = sigmoidf_(g1);
                e2 = sigmoidf_(g2); e3 = sigmoidf_(g3);
            }
            gsm[0 * 128 + c] = e0;
            gsm[1 * 128 + c] = e1;
            gsm[2 * 128 + c] = e2;
            gsm[3 * 128 + c] = e3;
        }
        __syncthreads();

        if (tid < 128) {
            float i_ = gsm[cb * 128 +  0 + cj];
            float f_ = gsm[cb * 128 + 32 + cj];
            float g_ = gsm[cb * 128 + 64 + cj];
            float o_ = gsm[cb * 128 + 96 + cj];
            cre = f_ * cre + i_ * g_;
            float hn = o_ * tanhf(cre);
            hlast = hn;
            out[((size_t)(b0 + cb) * 512 + t) * 256 + koff] = hn;

            // push h(t) to all 8 cluster CTAs' current buffer
            uint32_t loc = hsm_base +
                (uint32_t)((((t & 1) * 4 + cb) * 272 + cell_off) * 4);
#pragma unroll
            for (int pdst = 0; pdst < 8; ++pdst) {
                uint32_t ra;
                asm("mapa.shared::cluster.u32 %0, %1, %2;"
                    : "=r"(ra) : "r"(loc), "r"(pdst));
                asm volatile("st.shared::cluster.f32 [%0], %1;"
                             :: "r"(ra), "f"(hn) : "memory");
            }
        }

        // cluster barrier: release our pushes, acquire peers' pushes.
        asm volatile("barrier.cluster.arrive.aligned;" ::: "memory");
        asm volatile("barrier.cluster.wait.aligned;"   ::: "memory");
    }

    if (tid < 128) {
        out[8388608u + (size_t)(b0 + cb) * 256 + koff]          = hlast; // ht
        out[8388608u + 16384u + (size_t)(b0 + cb) * 256 + koff] = cre;   // ct
    }
}

// ---------------------------------------------------------------------------
extern "C" void kernel_launch(void* const* d_in, const int* in_sizes, int n_in,
                              void* d_out, int out_size) {
    const float* x  = nullptr;   // 64*512*128 = 4194304
    const float* Wi = nullptr;   // 128*1024   = 131072
    const float* Wh = nullptr;   // 256*1024   = 262144
    const float* Bb = nullptr;   // 1024
    for (int i = 0; i < n_in; ++i) {
        switch (in_sizes[i]) {
            case 4194304: x  = (const float*)d_in[i]; break;
            case 131072:  Wi = (const float*)d_in[i]; break;
            case 262144:  Wh = (const float*)d_in[i]; break;
            case 1024:    Bb = (const float*)d_in[i]; break;
            default: break;
        }
    }
    float* out = (float*)d_out;
    (void)out_size;

    xproj_kernel<<<dim3(16, 512), 256>>>(x, Wi, Bb);
    lstm_rec<<<128, 512>>>(Wh, out);
}

// round 4
// speedup vs baseline: 1.2024x; 1.0006x over previous
#include <cuda_runtime.h>
#include <cstdint>

// ---------------------------------------------------------------------------
// ChaoticLSTM: bs=64, seq=512, in=128, H=256, 4H=1024, T=512
//   Phase 1: xproj[32768][1024] = X[32768][128] @ Wi[128][1024] + B
//   Phase 2: register-stationary-Wh recurrence, 16 clusters x 8 CTAs x 512 thr.
//     CTA rank r owns h-dims [32r,32r+32). Warp w owns ALL 4 gates of h-dims
//     {2w, 2w+1}: lane = s*8 + cl, s = k-segment (64 k), ga = cl&3, jh = cl>>2.
//     Cell update is fully in-warp (shfl); no smem gate exchange, no
//     __syncthreads in the loop. One cluster barrier per step; out-store and
//     next-step xproj prefetch hide in the arrive->wait window.
// ---------------------------------------------------------------------------

typedef unsigned long long ull;

__device__ float g_xproj[32768u * 1024u];   // 128 MB scratch

__device__ __forceinline__ void fma2(ull& d, ull a, ull b) {
    asm("fma.rn.f32x2 %0, %1, %2, %0;" : "+l"(d) : "l"(a), "l"(b));
}
__device__ __forceinline__ ull splat2(float x) {
    ull r; asm("mov.b64 %0, {%1, %1};" : "=l"(r) : "f"(x)); return r;
}
__device__ __forceinline__ ull pack2(float a, float b) {
    ull r; asm("mov.b64 %0, {%1, %2};" : "=l"(r) : "f"(a), "f"(b)); return r;
}
__device__ __forceinline__ float2 unpack2(ull v) {
    float2 r; asm("mov.b64 {%0, %1}, %2;" : "=f"(r.x), "=f"(r.y) : "l"(v)); return r;
}
__device__ __forceinline__ float rcpf(float x) {
    float r; asm("rcp.approx.f32 %0, %1;" : "=f"(r) : "f"(x)); return r;
}
__device__ __forceinline__ uint32_t smem_u32(const void* p) {
    uint32_t a;
    asm("{ .reg .u64 t; cvta.to.shared.u64 t, %1; cvt.u32.u64 %0, t; }"
        : "=r"(a) : "l"(p));
    return a;
}

// ---------------------------------------------------------------------------
// Phase 1: xproj GEMM (unchanged; ~230us, not the bottleneck this round).
// ---------------------------------------------------------------------------
__global__ __launch_bounds__(256) void xproj_kernel(const float* __restrict__ X,
                                                    const float* __restrict__ Wi,
                                                    const float* __restrict__ Bias) {
    __shared__ __align__(16) float As_t[32 * 68];
    __shared__ __align__(16) float Bs[32 * 64];

    const int tid = threadIdx.x;
    const int m0 = blockIdx.y * 64;
    const int n0 = blockIdx.x * 64;
    const int tm = tid >> 4, tn = tid & 15;

    ull acc[4][2];
#pragma unroll
    for (int i = 0; i < 4; ++i) { acc[i][0] = 0ull; acc[i][1] = 0ull; }

    const float4* X4  = (const float4*)X;
    const float4* Wi4 = (const float4*)Wi;

    for (int kt = 0; kt < 128; kt += 32) {
#pragma unroll
        for (int i = 0; i < 2; ++i) {
            int f = tid + i * 256;
            int row = f >> 3, kk4 = f & 7;
            float4 v = X4[(size_t)(m0 + row) * 32 + (kt >> 2) + kk4];
            As_t[(kk4 * 4 + 0) * 68 + row] = v.x;
            As_t[(kk4 * 4 + 1) * 68 + row] = v.y;
            As_t[(kk4 * 4 + 2) * 68 + row] = v.z;
            As_t[(kk4 * 4 + 3) * 68 + row] = v.w;
        }
#pragma unroll
        for (int i = 0; i < 2; ++i) {
            int f = tid + i * 256;
            int row = f >> 4, c4 = f & 15;
            *(float4*)(Bs + row * 64 + c4 * 4) =
                Wi4[(size_t)(kt + row) * 256 + (n0 >> 2) + c4];
        }
        __syncthreads();
#pragma unroll
        for (int kk = 0; kk < 32; ++kk) {
            float4 a4 = *(const float4*)(As_t + kk * 68 + tm * 4);
            ulonglong2 b2 = *(const ulonglong2*)(Bs + kk * 64 + tn * 4);
            ull s;
            s = splat2(a4.x); fma2(acc[0][0], s, b2.x); fma2(acc[0][1], s, b2.y);
            s = splat2(a4.y); fma2(acc[1][0], s, b2.x); fma2(acc[1][1], s, b2.y);
            s = splat2(a4.z); fma2(acc[2][0], s, b2.x); fma2(acc[2][1], s, b2.y);
            s = splat2(a4.w); fma2(acc[3][0], s, b2.x); fma2(acc[3][1], s, b2.y);
        }
        __syncthreads();
    }

    float4 bias = *(const float4*)(Bias + n0 + tn * 4);
#pragma unroll
    for (int i = 0; i < 4; ++i) {
        float2 p0 = unpack2(acc[i][0]);
        float2 p1 = unpack2(acc[i][1]);
        float4 o = make_float4(p0.x + bias.x, p0.y + bias.y,
                               p1.x + bias.z, p1.y + bias.w);
        *(float4*)(g_xproj + (size_t)(m0 + tm * 4 + i) * 1024 + n0 + tn * 4) = o;
    }
}

// ---------------------------------------------------------------------------
// Phase 2: all-in-warp recurrence.
// ---------------------------------------------------------------------------
__global__ __launch_bounds__(512, 1) __cluster_dims__(8, 1, 1)
void lstm_rec(const float* __restrict__ Wh, float* __restrict__ out) {
    __shared__ __align__(16) float hsm[2 * 4 * 272];   // [buf][batch][4 seg x 68]

    const int tid  = threadIdx.x;
    const int lane = tid & 31;
    const int warp = tid >> 5;
    const int cl   = lane & 7;
    const int s    = lane >> 3;          // k-segment == my batch index
    const int ga   = cl & 3;             // gate
    const int jh   = cl >> 2;            // which of the warp's 2 h-dims

    uint32_t rank;
    asm("mov.u32 %0, %%cluster_ctarank;" : "=r"(rank));
    const int r     = (int)rank;
    const int b0    = (blockIdx.x >> 3) * 4;     // first batch of cluster
    const int jjl   = 2 * warp + jh;             // local h-dim 0..31
    const int koff  = r * 32 + jjl;              // global h index
    const int colg  = ga * 256 + koff;           // global gate column
    const int kbase = s * 64;

    // --- Wh slice -> registers (one-time) ---
    ull wreg[32];
#pragma unroll
    for (int i = 0; i < 32; ++i) {
        float wa = __ldg(&Wh[(size_t)(kbase + 2 * i) * 1024 + colg]);
        float wb = __ldg(&Wh[(size_t)(kbase + 2 * i + 1) * 1024 + colg]);
        wreg[i] = pack2(wa, wb);
    }

    // zero both h buffers; cluster-sync before any peer can push into buf0
    for (int i = tid; i < 2 * 4 * 272; i += 512) hsm[i] = 0.0f;
    __syncthreads();
    asm volatile("barrier.cluster.arrive.aligned;" ::: "memory");
    asm volatile("barrier.cluster.wait.aligned;"   ::: "memory");

    const uint32_t hsm_base  = smem_u32(hsm);
    const int      cell_off  = (koff >> 6) * 68 + (koff & 63);
    const uint32_t push_base = hsm_base + (uint32_t)(s * 272 + cell_off) * 4u;
    const int pd1 = ga, pd2 = ga + 4;            // my 2 push destinations

    // gate activation: i,f,o -> sigmoid(x); g -> tanh(x) = 2*sigmoid(2x)-1
    const float am = (ga == 2) ? 2.0f : 1.0f;
    const float om = (ga == 2) ? 2.0f : 1.0f;
    const float ob = (ga == 2) ? -1.0f : 0.0f;

    const unsigned base_src = (unsigned)(lane & 0x1C);   // s*8 + jh*4
    const bool     writer   = (ga == 0);                 // 1 of 4 redundant lanes

    const float* xpp  = g_xproj + (size_t)(b0 + s) * 512 * 1024 + colg;
    float*       outp = out + (size_t)(b0 + s) * 512 * 256 + koff;

    float xp  = __ldg(xpp);    // t = 0
    float cre = 0.0f;

#pragma unroll 1
    for (int t = 0; t < 512; ++t) {
        const float* hb = hsm + ((t + 1) & 1) * 1088;    // previous-h buffer
        const ulonglong2* h0 = (const ulonglong2*)(hb + 0 * 272 + s * 68);
        const ulonglong2* h1 = (const ulonglong2*)(hb + 1 * 272 + s * 68);
        const ulonglong2* h2 = (const ulonglong2*)(hb + 2 * 272 + s * 68);
        const ulonglong2* h3 = (const ulonglong2*)(hb + 3 * 272 + s * 68);

        ull a0 = 0, a1 = 0, a2 = 0, a3 = 0;
#pragma unroll
        for (int i = 0; i < 16; ++i) {
            ulonglong2 v0 = h0[i];
            ulonglong2 v1 = h1[i];
            ulonglong2 v2 = h2[i];
            ulonglong2 v3 = h3[i];
            fma2(a0, wreg[2 * i], v0.x); fma2(a0, wreg[2 * i + 1], v0.y);
            fma2(a1, wreg[2 * i], v1.x); fma2(a1, wreg[2 * i + 1], v1.y);
            fma2(a2, wreg[2 * i], v2.x); fma2(a2, wreg[2 * i + 1], v2.y);
            fma2(a3, wreg[2 * i], v3.x); fma2(a3, wreg[2 * i + 1], v3.y);
        }

        float2 p;
        float d0, d1, d2, d3;
        p = unpack2(a0); d0 = p.x + p.y;
        p = unpack2(a1); d1 = p.x + p.y;
        p = unpack2(a2); d2 = p.x + p.y;
        p = unpack2(a3); d3 = p.x + p.y;

        // reduce the 4 k-segment partials (lanes xor 8, 16)
        d0 += __shfl_xor_sync(0xffffffffu, d0, 8);
        d1 += __shfl_xor_sync(0xffffffffu, d1, 8);
        d2 += __shfl_xor_sync(0xffffffffu, d2, 8);
        d3 += __shfl_xor_sync(0xffffffffu, d3, 8);
        d0 += __shfl_xor_sync(0xffffffffu, d0, 16);
        d1 += __shfl_xor_sync(0xffffffffu, d1, 16);
        d2 += __shfl_xor_sync(0xffffffffu, d2, 16);
        d3 += __shfl_xor_sync(0xffffffffu, d3, 16);

        // my batch's gate pre-activation, then branchless activation
        float ds = (s == 0) ? d0 : (s == 1) ? d1 : (s == 2) ? d2 : d3;
        float gx = xp + ds;
        float u  = __expf(-am * gx);
        float sg = rcpf(1.0f + u);
        float e  = fmaf(sg, om, ob);

        // gather i,f,g,o for (batch s, h-dim jh) entirely in-warp
        float i_ = __shfl_sync(0xffffffffu, e, base_src | 0);
        float f_ = __shfl_sync(0xffffffffu, e, base_src | 1);
        float g_ = __shfl_sync(0xffffffffu, e, base_src | 2);
        float o_ = __shfl_sync(0xffffffffu, e, base_src | 3);

        cre = fmaf(f_, cre, i_ * g_);
        float u2 = __expf(-2.0f * cre);
        float th = (1.0f - u2) * rcpf(1.0f + u2);   // tanh(cre)
        float hn = o_ * th;

        // push h(t) to 2 of the 8 cluster CTAs (4 redundant lanes x 2 = 8)
        uint32_t loc = push_base + (uint32_t)((t & 1) * (1088 * 4));
        uint32_t ra;
        asm("mapa.shared::cluster.u32 %0, %1, %2;" : "=r"(ra) : "r"(loc), "r"(pd1));
        asm volatile("st.shared::cluster.f32 [%0], %1;" :: "r"(ra), "f"(hn) : "memory");
        asm("mapa.shared::cluster.u32 %0, %1, %2;" : "=r"(ra) : "r"(loc), "r"(pd2));
        asm volatile("st.shared::cluster.f32 [%0], %1;" :: "r"(ra), "f"(hn) : "memory");

        asm volatile("barrier.cluster.arrive.aligned;" ::: "memory");

        // off-critical-path work inside the arrive->wait window
        if (writer) outp[(size_t)t * 256] = hn;
        float xpn = 0.0f;
        if (t < 511) {
            xpn = __ldg(xpp + (size_t)(t + 1) * 1024);
        } else if (writer) {
            out[8388608u + (size_t)(b0 + s) * 256 + koff]          = hn;   // ht
            out[8388608u + 16384u + (size_t)(b0 + s) * 256 + koff] = cre;  // ct
        }

        asm volatile("barrier.cluster.wait.aligned;" ::: "memory");
        xp = xpn;
    }
}

// ---------------------------------------------------------------------------
extern "C" void kernel_launch(void* const* d_in, const int* in_sizes, int n_in,
                              void* d_out, int out_size) {
    const float* x  = nullptr;   // 64*512*128 = 4194304
    const float* Wi = nullptr;   // 128*1024   = 131072
    const float* Wh = nullptr;   // 256*1024   = 262144
    const float* Bb = nullptr;   // 1024
    for (int i = 0; i < n_in; ++i) {
        switch (in_sizes[i]) {
            case 4194304: x  = (const float*)d_in[i]; break;
            case 131072:  Wi = (const float*)d_in[i]; break;
            case 262144:  Wh = (const float*)d_in[i]; break;
            case 1024:    Bb = (const float*)d_in[i]; break;
            default: break;
        }
    }
    float* out = (float*)d_out;
    (void)out_size;

    xproj_kernel<<<dim3(16, 512), 256>>>(x, Wi, Bb);
    lstm_rec<<<128, 512>>>(Wh, out);
}